// round 16
// baseline (speedup 1.0000x reference)
#include <cuda_runtime.h>
#include <math_constants.h>

#define BATCH 8
#define HH 224
#define WW 224
#define OH 223
#define OW 223
#define NR 16            // min/max slices per batch (K1 CTAs per batch)
#define RV4 1568         // 25088 float4 per batch / 16
#define NPIX (33 * 33)   // 1089 halo pixels
#define PI_F 3.14159265358979323846f

// Per-(batch,slice) {min,max}. Written by K1 every launch, read by K2 after
// the PDL dependency — no atomics, no counters, no reset.
__device__ float2 g_slot[BATCH][NR];

static __device__ __forceinline__ float2 ldcg_f2(const float2* p) {
    float2 v;
    asm volatile("ld.global.cg.v2.f32 {%0,%1}, [%2];"
                 : "=f"(v.x), "=f"(v.y) : "l"(p) : "memory");
    return v;
}
static __device__ __forceinline__ void stcg_f2(float2* p, float a, float b) {
    asm volatile("st.global.cg.v2.f32 [%0], {%1,%2};"
                 :: "l"(p), "f"(a), "f"(b) : "memory");
}

// ---- K1: per-slice min/max (coalesced float4), 128 CTAs ----
__global__ void __launch_bounds__(256)
minmax_k(const float* __restrict__ x) {
    __shared__ float sred[16];
    const int slice = blockIdx.x;       // 0..15
    const int b     = blockIdx.y;
    const int tid   = threadIdx.x;

    const float4* xv = (const float4*)(x + (size_t)b * 2 * HH * WW) + slice * RV4;
    float lmin = CUDART_INF_F, lmax = -CUDART_INF_F;
    #pragma unroll
    for (int j = 0; j < 7; j++) {        // 1568 = 6*256 + 32
        int i = j * 256 + tid;
        if (i < RV4) {
            float4 v = xv[i];
            lmin = fminf(lmin, fminf(fminf(v.x, v.y), fminf(v.z, v.w)));
            lmax = fmaxf(lmax, fmaxf(fmaxf(v.x, v.y), fmaxf(v.z, v.w)));
        }
    }
    #pragma unroll
    for (int off = 16; off > 0; off >>= 1) {
        lmin = fminf(lmin, __shfl_xor_sync(0xFFFFFFFFu, lmin, off));
        lmax = fmaxf(lmax, __shfl_xor_sync(0xFFFFFFFFu, lmax, off));
    }
    if ((tid & 31) == 0) { sred[tid >> 5] = lmin; sred[8 + (tid >> 5)] = lmax; }
    __syncthreads();
    if (tid == 0) {
        float m0 = sred[0], m1 = sred[8];
        #pragma unroll
        for (int i = 1; i < 8; i++) {
            m0 = fminf(m0, sred[i]);
            m1 = fmaxf(m1, sred[8 + i]);
        }
        stcg_f2(&g_slot[b][slice], m0, m1);
        __threadfence();                 // slot visible before dependents proceed
    }
    __syncthreads();
    // Allow the dependent grid to proceed once all K1 blocks reach here.
    asm volatile("griddepcontrol.launch_dependents;");
}

// ---- K2: main compute; overlaps its ramp/prefetch with K1 via PDL ----
__global__ void __launch_bounds__(256)
quanv_k(const float* __restrict__ x, const float* __restrict__ wts,
        float* __restrict__ out) {
    __shared__ float2 sTS[NPIX];         // {t = cos(a)cos(b), s = sin(a)}
    __shared__ float s_fmn, s_scale;
    __shared__ float s_cw[4], s_sw[4];

    const int b   = blockIdx.z;
    const int tid = threadIdx.x;
    const int r0  = blockIdx.y * 32;
    const int c0  = blockIdx.x * 32;

    if (tid < 4) {
        float w = wts[tid];              // reads input only — legal pre-wait
        s_cw[tid] = cosf(w);
        s_sw[tid] = sinf(w);
    }

    const float* x0 = x + (size_t)b * 2 * HH * WW;
    const float* x1 = x0 + HH * WW;

    // ---- Prefetch halo pixels BEFORE the dependency wait (reads input only) ----
    float ra[5], rb[5];
    #pragma unroll
    for (int j = 0; j < 5; j++) {
        int i = tid + j * 256;
        if (i < NPIX) {
            int rr = i / 33, cc = i - rr * 33;
            int r = min(r0 + rr, HH - 1);
            int c = min(c0 + cc, WW - 1);
            ra[j] = __ldg(x0 + r * WW + c);
            rb[j] = __ldg(x1 + r * WW + c);
        }
    }

    // ---- Wait for K1's slots to be visible ----
    asm volatile("griddepcontrol.wait;" ::: "memory");

    if (tid < 32) {
        float pm = CUDART_INF_F, px = -CUDART_INF_F;
        if (tid < NR) {
            float2 v = ldcg_f2(&g_slot[b][tid]);
            pm = v.x; px = v.y;
        }
        #pragma unroll
        for (int off = 8; off > 0; off >>= 1) {
            pm = fminf(pm, __shfl_xor_sync(0xFFFFFFFFu, pm, off));
            px = fmaxf(px, __shfl_xor_sync(0xFFFFFFFFu, px, off));
        }
        if (tid == 0) {
            s_fmn = pm;
            s_scale = PI_F / (px - pm + 1e-8f);
        }
    }
    __syncthreads();

    const float scale = s_scale;
    const float nmn = -s_fmn * scale;    // a = fma(v, scale, nmn)

    // ---- Transform registers -> packed smem ----
    #pragma unroll
    for (int j = 0; j < 5; j++) {
        int i = tid + j * 256;
        if (i < NPIX) {
            float a  = fmaf(ra[j], scale, nmn);
            float bb = fmaf(rb[j], scale, nmn);
            float sa, ca;
            __sincosf(a, &sa, &ca);
            sTS[i] = make_float2(ca * __cosf(bb), sa);
        }
    }
    __syncthreads();

    // ---- Output: z_i = cw_i*t - sw_i*s at 4 corners, parity products ----
    const float cw0 = s_cw[0], sw0 = s_sw[0];
    const float cw1 = s_cw[1], sw1 = s_sw[1];
    const float cw2 = s_cw[2], sw2 = s_sw[2];
    const float cw3 = s_cw[3], sw3 = s_sw[3];

    const int tx = tid & 31;
    const int ty = tid >> 5;
    const size_t plane = (size_t)OH * OW;
    float* ob = out + (size_t)b * 4 * plane;

    #pragma unroll
    for (int k = 0; k < 4; k++) {
        int ly = ty * 4 + k;
        int oh = r0 + ly;
        int ow = c0 + tx;
        if (oh < OH && ow < OW) {
            int p = ly * 33 + tx;
            float2 v0 = sTS[p];
            float2 v1 = sTS[p + 1];
            float2 v2 = sTS[p + 33];
            float2 v3 = sTS[p + 34];
            float z0 = fmaf(cw0, v0.x, -sw0 * v0.y);
            float z1 = fmaf(cw1, v1.x, -sw1 * v1.y);
            float z2 = fmaf(cw2, v2.x, -sw2 * v2.y);
            float z3 = fmaf(cw3, v3.x, -sw3 * v3.y);
            float z01 = z0 * z1;
            float z23 = z2 * z3;
            size_t o = (size_t)oh * OW + ow;
            ob[0 * plane + o] = z1 * z23;   // <Z0> = z1 z2 z3
            ob[1 * plane + o] = z01;        // <Z1> = z0 z1
            ob[2 * plane + o] = z01 * z2;   // <Z2> = z0 z1 z2
            ob[3 * plane + o] = z01 * z23;  // <Z3> = z0 z1 z2 z3
        }
    }
}

extern "C" void kernel_launch(void* const* d_in, const int* in_sizes, int n_in,
                              void* d_out, int out_size) {
    const float* x   = (const float*)d_in[0];   // [8,2,224,224]
    const float* wts = (const float*)d_in[1];   // [1,4]
    float* out = (float*)d_out;                 // [8,4,223,223]

    // K1: normal launch
    minmax_k<<<dim3(NR, BATCH), 256>>>(x);

    // K2: programmatic stream serialization — may launch while K1 runs;
    // synchronizes via griddepcontrol.wait inside the kernel.
    cudaLaunchAttribute attrs[1];
    attrs[0].id = cudaLaunchAttributeProgrammaticStreamSerialization;
    attrs[0].val.programmaticStreamSerializationAllowed = 1;

    cudaLaunchConfig_t cfg = {};
    cfg.gridDim = dim3(7, 7, BATCH);
    cfg.blockDim = dim3(256, 1, 1);
    cfg.dynamicSmemBytes = 0;
    cfg.stream = 0;
    cfg.attrs = attrs;
    cfg.numAttrs = 1;

    cudaLaunchKernelEx(&cfg, quanv_k, x, wts, out);
}